// round 13
// baseline (speedup 1.0000x reference)
#include <cuda_runtime.h>
#include <cstdint>

// GraphProjection, monolithic. History:
//  R4 coalesced scalar 90.1 -> R9 Cauchy zero shortcut 71.3 -> R10 aligned
//  zero-fill 69.7 -> R12 warp-uniform clip-collapse variants 67.6us.
// Analysis: slow-path store misalignment (60 wf vs 30) is structurally
// irreducible (shfl/smem/TMA all route the same bytes through the same
// 128B/cyc L1 port; misaligned LDG.128 illegal). R13: execution-shape tune:
// 128-thread blocks (fast/slow tail imbalance) + largest-level-first issue.

static constexpr int OUT_COLS = 963;

template <int C, int S>
__device__ __forceinline__ void bilerp_scalar(const float* __restrict__ feat,
                                              float x, float y,
                                              float* __restrict__ o, int lane) {
    float x1f = floorf(x), x2f = ceilf(x);
    float y1f = floorf(y), y2f = ceilf(y);
    int xi1 = (int)x1f, xi2 = (int)x2f, yi1 = (int)y1f, yi2 = (int)y2f;
    // JAX gather clamps; lower clamp also guards NaN->int conversion.
    if (xi1 < 0) xi1 = 0;
    if (yi1 < 0) yi1 = 0;
    if (xi2 < 0) xi2 = 0;
    if (yi2 < 0) yi2 = 0;
    if (xi1 > S - 1) xi1 = S - 1;
    if (yi1 > S - 1) yi1 = S - 1;
    if (xi2 > S - 1) xi2 = S - 1;
    if (yi2 > S - 1) yi2 = S - 1;

    float wa = (x2f - x) * (y2f - y);   // w11
    float wb = (x - x1f) * (y2f - y);   // w21
    float wc = (x2f - x) * (y - y1f);   // w12
    float wd = (x - x1f) * (y - y1f);   // w22

    const float* A = feat + (xi1 * S + yi1) * C;
    const float* B = feat + (xi2 * S + yi1) * C;
    const float* Cc = feat + (xi1 * S + yi2) * C;
    const float* D = feat + (xi2 * S + yi2) * C;

    bool xc = (xi1 == xi2);   // rows collapse (B==A, D==C)
    bool yc = (yi1 == yi2);   // cols collapse (C==A, D==B)

    if (xc && yc) {
        float wf = (wa + wb) + (wc + wd);
#pragma unroll
        for (int i = 0; i < C / 32; ++i) {
            int c = lane + 32 * i;
            o[c] = wf * __ldg(A + c);
        }
    } else if (xc) {
        float w0 = wa + wb, w1 = wc + wd;
#pragma unroll
        for (int i = 0; i < C / 32; ++i) {
            int c = lane + 32 * i;
            float a = __ldg(A + c);
            float cv = __ldg(Cc + c);
            o[c] = w0 * a + w1 * cv;
        }
    } else if (yc) {
        float w0 = wa + wc, w1 = wb + wd;
#pragma unroll
        for (int i = 0; i < C / 32; ++i) {
            int c = lane + 32 * i;
            float a = __ldg(A + c);
            float b = __ldg(B + c);
            o[c] = w0 * a + w1 * b;
        }
    } else {
#pragma unroll
        for (int i = 0; i < C / 32; ++i) {
            int c = lane + 32 * i;
            float a = __ldg(A + c);
            float b = __ldg(B + c);
            float cv = __ldg(Cc + c);
            float d = __ldg(D + c);
            o[c] = wa * a + wb * b + wc * cv + wd * d;
        }
    }
}

__global__ void __launch_bounds__(128)
graph_projection_kernel(const float* __restrict__ coord,
                        const float* __restrict__ f1,
                        const float* __restrict__ f2,
                        const float* __restrict__ f3,
                        const float* __restrict__ f4,
                        float* __restrict__ out, int N) {
    int p = (blockIdx.x * blockDim.x + threadIdx.x) >> 5;  // warp = point
    int lane = threadIdx.x & 31;
    if (p >= N) return;

    float X = __ldg(coord + 3 * p + 0);
    float Y = __ldg(coord + 3 * p + 1);
    float Z = __ldg(coord + 3 * p + 2);

    float h = 250.0f * (-Y) / (-Z) + 112.0f;
    float w = 250.0f * X / (-Z) + 112.0f;
    // clip to [0,223]; comparison form preserves jnp.clip NaN propagation
    h = (h < 0.0f) ? 0.0f : ((h > 223.0f) ? 223.0f : h);
    w = (w < 0.0f) ? 0.0f : ((w > 223.0f) ? 223.0f : w);

    float* __restrict__ orow = out + (size_t)p * OUT_COLS;
    if (lane == 0) orow[0] = X;
    if (lane == 1) orow[1] = Y;
    if (lane == 2) orow[2] = Z;

    // Fast path: h==0 or w==0 => x (or y) integral at every level =>
    // all four bilinear weights exactly 0 => 960-channel block is 0.
    if (h == 0.0f || w == 0.0f) {
        float* z = orow + 3;
        int head = (int)(((16u - ((uint32_t)(uintptr_t)z & 15u)) & 15u) >> 2);
        if (lane < head) z[lane] = 0.0f;
        int nvec = (960 - head) >> 2;
        float4* v = (float4*)(z + head);
        float4 z4 = make_float4(0.f, 0.f, 0.f, 0.f);
#pragma unroll
        for (int i = 0; i < 8; ++i) {
            int idx = lane + 32 * i;
            if (idx < nvec) v[idx] = z4;
        }
        int done = head + 4 * nvec;
        if (lane < 960 - done) z[done + lane] = 0.0f;
        return;
    }

    // scales: 224/56=4, 224/28=8, 224/14=16, 224/7=32 (exact pow2 -> mul ok)
    // Largest level first: front-load the longest load streams.
    bilerp_scalar<512, 7>(f4, h * 0.03125f, w * 0.03125f, orow + 451, lane);
    bilerp_scalar<256, 14>(f3, h * 0.0625f, w * 0.0625f,  orow + 195, lane);
    bilerp_scalar<128, 28>(f2, h * 0.125f,  w * 0.125f,   orow + 67,  lane);
    bilerp_scalar<64, 56>(f1, h * 0.25f,    w * 0.25f,    orow + 3,   lane);
}

extern "C" void kernel_launch(void* const* d_in, const int* in_sizes, int n_in,
                              void* d_out, int out_size) {
    const float* coord = (const float*)d_in[0];
    const float* f1 = (const float*)d_in[1];
    const float* f2 = (const float*)d_in[2];
    const float* f3 = (const float*)d_in[3];
    const float* f4 = (const float*)d_in[4];
    float* out = (float*)d_out;

    int N = in_sizes[0] / 3;

    int blocks = (N + 3) / 4;  // 4 warps/block, 1 point/warp
    graph_projection_kernel<<<blocks, 128>>>(coord, f1, f2, f3, f4, out, N);
}

// round 14
// speedup vs baseline: 1.0341x; 1.0341x over previous
#include <cuda_runtime.h>
#include <cstdint>

// GraphProjection, monolithic. History:
//  R4 coalesced scalar 90.1 -> R9 Cauchy zero shortcut 71.3 -> R10 aligned
//  zero-fill 69.7 -> R12 warp-uniform clip-collapse 67.6 (best).
//  R13 shape tweaks (128thr, level order) slightly negative -> reverted.
// R14: parity pairs. Row start 963p: for ODD p every level base (==3 mod 4)
// is at an EVEN float offset -> 8B aligned. Odd points use float2:
// LDG.64 loads (half the insts, same wf) + aligned STG.64 stores
// (~30 store wf vs 62, line-minimal, no cross-lane traffic needed).
// Even points keep the scalar path. Warp-uniform branch (p per warp).

static constexpr int OUT_COLS = 963;

struct PrepOut {
    const float* A;
    const float* B;
    const float* Cc;
    const float* D;
    float wa, wb, wc, wd;
    bool xc, yc;
};

template <int C, int S>
__device__ __forceinline__ PrepOut prep(const float* __restrict__ feat,
                                        float x, float y) {
    float x1f = floorf(x), x2f = ceilf(x);
    float y1f = floorf(y), y2f = ceilf(y);
    int xi1 = (int)x1f, xi2 = (int)x2f, yi1 = (int)y1f, yi2 = (int)y2f;
    // JAX gather clamps; lower clamp also guards NaN->int conversion.
    if (xi1 < 0) xi1 = 0;
    if (yi1 < 0) yi1 = 0;
    if (xi2 < 0) xi2 = 0;
    if (yi2 < 0) yi2 = 0;
    if (xi1 > S - 1) xi1 = S - 1;
    if (yi1 > S - 1) yi1 = S - 1;
    if (xi2 > S - 1) xi2 = S - 1;
    if (yi2 > S - 1) yi2 = S - 1;
    PrepOut r;
    r.wa = (x2f - x) * (y2f - y);
    r.wb = (x - x1f) * (y2f - y);
    r.wc = (x2f - x) * (y - y1f);
    r.wd = (x - x1f) * (y - y1f);
    r.A = feat + (xi1 * S + yi1) * C;
    r.B = feat + (xi2 * S + yi1) * C;
    r.Cc = feat + (xi1 * S + yi2) * C;
    r.D = feat + (xi2 * S + yi2) * C;
    r.xc = (xi1 == xi2);
    r.yc = (yi1 == yi2);
    return r;
}

// Scalar path (even p): coalesced LDG.32/STG.32, collapse variants.
template <int C, int S>
__device__ __forceinline__ void bilerp_scalar(const float* __restrict__ feat,
                                              float x, float y,
                                              float* __restrict__ o, int lane) {
    PrepOut t = prep<C, S>(feat, x, y);
    if (t.xc && t.yc) {
        float wf = (t.wa + t.wb) + (t.wc + t.wd);
#pragma unroll
        for (int i = 0; i < C / 32; ++i) {
            int c = lane + 32 * i;
            o[c] = wf * __ldg(t.A + c);
        }
    } else if (t.xc) {
        float w0 = t.wa + t.wb, w1 = t.wc + t.wd;
#pragma unroll
        for (int i = 0; i < C / 32; ++i) {
            int c = lane + 32 * i;
            float a = __ldg(t.A + c);
            float cv = __ldg(t.Cc + c);
            o[c] = w0 * a + w1 * cv;
        }
    } else if (t.yc) {
        float w0 = t.wa + t.wc, w1 = t.wb + t.wd;
#pragma unroll
        for (int i = 0; i < C / 32; ++i) {
            int c = lane + 32 * i;
            float a = __ldg(t.A + c);
            float b = __ldg(t.B + c);
            o[c] = w0 * a + w1 * b;
        }
    } else {
#pragma unroll
        for (int i = 0; i < C / 32; ++i) {
            int c = lane + 32 * i;
            float a = __ldg(t.A + c);
            float b = __ldg(t.B + c);
            float cv = __ldg(t.Cc + c);
            float d = __ldg(t.D + c);
            o[c] = t.wa * a + t.wb * b + t.wc * cv + t.wd * d;
        }
    }
}

// Pair path (odd p): LDG.64 + aligned STG.64, collapse variants.
template <int C, int S>
__device__ __forceinline__ void bilerp_pair(const float* __restrict__ feat,
                                            float x, float y,
                                            float* __restrict__ o, int lane) {
    PrepOut t = prep<C, S>(feat, x, y);
    const float2* A2 = (const float2*)t.A;
    const float2* B2 = (const float2*)t.B;
    const float2* C2 = (const float2*)t.Cc;
    const float2* D2 = (const float2*)t.D;
    if (t.xc && t.yc) {
        float wf = (t.wa + t.wb) + (t.wc + t.wd);
#pragma unroll
        for (int i = 0; i < C / 64; ++i) {
            int c2 = lane + 32 * i;
            float2 a = __ldg(A2 + c2);
            float2 r = make_float2(wf * a.x, wf * a.y);
            *(float2*)(o + 2 * c2) = r;
        }
    } else if (t.xc) {
        float w0 = t.wa + t.wb, w1 = t.wc + t.wd;
#pragma unroll
        for (int i = 0; i < C / 64; ++i) {
            int c2 = lane + 32 * i;
            float2 a = __ldg(A2 + c2);
            float2 cv = __ldg(C2 + c2);
            float2 r = make_float2(w0 * a.x + w1 * cv.x, w0 * a.y + w1 * cv.y);
            *(float2*)(o + 2 * c2) = r;
        }
    } else if (t.yc) {
        float w0 = t.wa + t.wc, w1 = t.wb + t.wd;
#pragma unroll
        for (int i = 0; i < C / 64; ++i) {
            int c2 = lane + 32 * i;
            float2 a = __ldg(A2 + c2);
            float2 b = __ldg(B2 + c2);
            float2 r = make_float2(w0 * a.x + w1 * b.x, w0 * a.y + w1 * b.y);
            *(float2*)(o + 2 * c2) = r;
        }
    } else {
#pragma unroll
        for (int i = 0; i < C / 64; ++i) {
            int c2 = lane + 32 * i;
            float2 a = __ldg(A2 + c2);
            float2 b = __ldg(B2 + c2);
            float2 cv = __ldg(C2 + c2);
            float2 d = __ldg(D2 + c2);
            float2 r = make_float2(
                t.wa * a.x + t.wb * b.x + t.wc * cv.x + t.wd * d.x,
                t.wa * a.y + t.wb * b.y + t.wc * cv.y + t.wd * d.y);
            *(float2*)(o + 2 * c2) = r;
        }
    }
}

__global__ void __launch_bounds__(256)
graph_projection_kernel(const float* __restrict__ coord,
                        const float* __restrict__ f1,
                        const float* __restrict__ f2,
                        const float* __restrict__ f3,
                        const float* __restrict__ f4,
                        float* __restrict__ out, int N) {
    int p = (blockIdx.x * blockDim.x + threadIdx.x) >> 5;  // warp = point
    int lane = threadIdx.x & 31;
    if (p >= N) return;

    float X = __ldg(coord + 3 * p + 0);
    float Y = __ldg(coord + 3 * p + 1);
    float Z = __ldg(coord + 3 * p + 2);

    float h = 250.0f * (-Y) / (-Z) + 112.0f;
    float w = 250.0f * X / (-Z) + 112.0f;
    // clip to [0,223]; comparison form preserves jnp.clip NaN propagation
    h = (h < 0.0f) ? 0.0f : ((h > 223.0f) ? 223.0f : h);
    w = (w < 0.0f) ? 0.0f : ((w > 223.0f) ? 223.0f : w);

    float* __restrict__ orow = out + (size_t)p * OUT_COLS;
    if (lane == 0) orow[0] = X;
    if (lane == 1) orow[1] = Y;
    if (lane == 2) orow[2] = Z;

    // Fast path: h==0 or w==0 => all bilinear weights exactly 0.
    if (h == 0.0f || w == 0.0f) {
        float* z = orow + 3;
        int head = (int)(((16u - ((uint32_t)(uintptr_t)z & 15u)) & 15u) >> 2);
        if (lane < head) z[lane] = 0.0f;
        int nvec = (960 - head) >> 2;
        float4* v = (float4*)(z + head);
        float4 z4 = make_float4(0.f, 0.f, 0.f, 0.f);
#pragma unroll
        for (int i = 0; i < 8; ++i) {
            int idx = lane + 32 * i;
            if (idx < nvec) v[idx] = z4;
        }
        int done = head + 4 * nvec;
        if (lane < 960 - done) z[done + lane] = 0.0f;
        return;
    }

    // scales: 224/56=4, 224/28=8, 224/14=16, 224/7=32 (exact pow2 -> mul ok)
    if (p & 1) {
        // odd p: 963p+base even for all bases (3,67,195,451) -> 8B aligned
        bilerp_pair<64, 56>(f1, h * 0.25f,    w * 0.25f,    orow + 3,   lane);
        bilerp_pair<128, 28>(f2, h * 0.125f,  w * 0.125f,   orow + 67,  lane);
        bilerp_pair<256, 14>(f3, h * 0.0625f, w * 0.0625f,  orow + 195, lane);
        bilerp_pair<512, 7>(f4, h * 0.03125f, w * 0.03125f, orow + 451, lane);
    } else {
        bilerp_scalar<64, 56>(f1, h * 0.25f,    w * 0.25f,    orow + 3,   lane);
        bilerp_scalar<128, 28>(f2, h * 0.125f,  w * 0.125f,   orow + 67,  lane);
        bilerp_scalar<256, 14>(f3, h * 0.0625f, w * 0.0625f,  orow + 195, lane);
        bilerp_scalar<512, 7>(f4, h * 0.03125f, w * 0.03125f, orow + 451, lane);
    }
}

extern "C" void kernel_launch(void* const* d_in, const int* in_sizes, int n_in,
                              void* d_out, int out_size) {
    const float* coord = (const float*)d_in[0];
    const float* f1 = (const float*)d_in[1];
    const float* f2 = (const float*)d_in[2];
    const float* f3 = (const float*)d_in[3];
    const float* f4 = (const float*)d_in[4];
    float* out = (float*)d_out;

    int N = in_sizes[0] / 3;

    int blocks = (N + 7) / 8;  // 8 warps/block, 1 point/warp
    graph_projection_kernel<<<blocks, 256>>>(coord, f1, f2, f3, f4, out, N);
}

// round 15
// speedup vs baseline: 1.0936x; 1.0576x over previous
#include <cuda_runtime.h>
#include <cstdint>

// GraphProjection, monolithic. History:
//  R4 coalesced scalar 90.1 -> R9 Cauchy zero shortcut 71.3 -> R10 aligned
//  zero-fill 69.7 -> R12 warp-uniform clip-collapse 67.6 -> R14 parity
//  pairs 67.6 (tie). Two shapes, same time + steady-state write stream
//  385MB/67.6us = 5.7TB/s => DRAM-write-floor bound. R15: mark all output
//  stores streaming (__stcs, evict-first) to cut L2 pollution by the
//  write-once output; structure unchanged from R14.

static constexpr int OUT_COLS = 963;

struct PrepOut {
    const float* A;
    const float* B;
    const float* Cc;
    const float* D;
    float wa, wb, wc, wd;
    bool xc, yc;
};

template <int C, int S>
__device__ __forceinline__ PrepOut prep(const float* __restrict__ feat,
                                        float x, float y) {
    float x1f = floorf(x), x2f = ceilf(x);
    float y1f = floorf(y), y2f = ceilf(y);
    int xi1 = (int)x1f, xi2 = (int)x2f, yi1 = (int)y1f, yi2 = (int)y2f;
    // JAX gather clamps; lower clamp also guards NaN->int conversion.
    if (xi1 < 0) xi1 = 0;
    if (yi1 < 0) yi1 = 0;
    if (xi2 < 0) xi2 = 0;
    if (yi2 < 0) yi2 = 0;
    if (xi1 > S - 1) xi1 = S - 1;
    if (yi1 > S - 1) yi1 = S - 1;
    if (xi2 > S - 1) xi2 = S - 1;
    if (yi2 > S - 1) yi2 = S - 1;
    PrepOut r;
    r.wa = (x2f - x) * (y2f - y);
    r.wb = (x - x1f) * (y2f - y);
    r.wc = (x2f - x) * (y - y1f);
    r.wd = (x - x1f) * (y - y1f);
    r.A = feat + (xi1 * S + yi1) * C;
    r.B = feat + (xi2 * S + yi1) * C;
    r.Cc = feat + (xi1 * S + yi2) * C;
    r.D = feat + (xi2 * S + yi2) * C;
    r.xc = (xi1 == xi2);
    r.yc = (yi1 == yi2);
    return r;
}

// Scalar path (even p): coalesced LDG.32 + streaming STG.32.
template <int C, int S>
__device__ __forceinline__ void bilerp_scalar(const float* __restrict__ feat,
                                              float x, float y,
                                              float* __restrict__ o, int lane) {
    PrepOut t = prep<C, S>(feat, x, y);
    if (t.xc && t.yc) {
        float wf = (t.wa + t.wb) + (t.wc + t.wd);
#pragma unroll
        for (int i = 0; i < C / 32; ++i) {
            int c = lane + 32 * i;
            __stcs(o + c, wf * __ldg(t.A + c));
        }
    } else if (t.xc) {
        float w0 = t.wa + t.wb, w1 = t.wc + t.wd;
#pragma unroll
        for (int i = 0; i < C / 32; ++i) {
            int c = lane + 32 * i;
            float a = __ldg(t.A + c);
            float cv = __ldg(t.Cc + c);
            __stcs(o + c, w0 * a + w1 * cv);
        }
    } else if (t.yc) {
        float w0 = t.wa + t.wc, w1 = t.wb + t.wd;
#pragma unroll
        for (int i = 0; i < C / 32; ++i) {
            int c = lane + 32 * i;
            float a = __ldg(t.A + c);
            float b = __ldg(t.B + c);
            __stcs(o + c, w0 * a + w1 * b);
        }
    } else {
#pragma unroll
        for (int i = 0; i < C / 32; ++i) {
            int c = lane + 32 * i;
            float a = __ldg(t.A + c);
            float b = __ldg(t.B + c);
            float cv = __ldg(t.Cc + c);
            float d = __ldg(t.D + c);
            __stcs(o + c, t.wa * a + t.wb * b + t.wc * cv + t.wd * d);
        }
    }
}

// Pair path (odd p): LDG.64 + aligned streaming STG.64.
template <int C, int S>
__device__ __forceinline__ void bilerp_pair(const float* __restrict__ feat,
                                            float x, float y,
                                            float* __restrict__ o, int lane) {
    PrepOut t = prep<C, S>(feat, x, y);
    const float2* A2 = (const float2*)t.A;
    const float2* B2 = (const float2*)t.B;
    const float2* C2 = (const float2*)t.Cc;
    const float2* D2 = (const float2*)t.D;
    if (t.xc && t.yc) {
        float wf = (t.wa + t.wb) + (t.wc + t.wd);
#pragma unroll
        for (int i = 0; i < C / 64; ++i) {
            int c2 = lane + 32 * i;
            float2 a = __ldg(A2 + c2);
            __stcs((float2*)(o + 2 * c2), make_float2(wf * a.x, wf * a.y));
        }
    } else if (t.xc) {
        float w0 = t.wa + t.wb, w1 = t.wc + t.wd;
#pragma unroll
        for (int i = 0; i < C / 64; ++i) {
            int c2 = lane + 32 * i;
            float2 a = __ldg(A2 + c2);
            float2 cv = __ldg(C2 + c2);
            __stcs((float2*)(o + 2 * c2),
                   make_float2(w0 * a.x + w1 * cv.x, w0 * a.y + w1 * cv.y));
        }
    } else if (t.yc) {
        float w0 = t.wa + t.wc, w1 = t.wb + t.wd;
#pragma unroll
        for (int i = 0; i < C / 64; ++i) {
            int c2 = lane + 32 * i;
            float2 a = __ldg(A2 + c2);
            float2 b = __ldg(B2 + c2);
            __stcs((float2*)(o + 2 * c2),
                   make_float2(w0 * a.x + w1 * b.x, w0 * a.y + w1 * b.y));
        }
    } else {
#pragma unroll
        for (int i = 0; i < C / 64; ++i) {
            int c2 = lane + 32 * i;
            float2 a = __ldg(A2 + c2);
            float2 b = __ldg(B2 + c2);
            float2 cv = __ldg(C2 + c2);
            float2 d = __ldg(D2 + c2);
            __stcs((float2*)(o + 2 * c2),
                   make_float2(
                       t.wa * a.x + t.wb * b.x + t.wc * cv.x + t.wd * d.x,
                       t.wa * a.y + t.wb * b.y + t.wc * cv.y + t.wd * d.y));
        }
    }
}

__global__ void __launch_bounds__(256)
graph_projection_kernel(const float* __restrict__ coord,
                        const float* __restrict__ f1,
                        const float* __restrict__ f2,
                        const float* __restrict__ f3,
                        const float* __restrict__ f4,
                        float* __restrict__ out, int N) {
    int p = (blockIdx.x * blockDim.x + threadIdx.x) >> 5;  // warp = point
    int lane = threadIdx.x & 31;
    if (p >= N) return;

    float X = __ldg(coord + 3 * p + 0);
    float Y = __ldg(coord + 3 * p + 1);
    float Z = __ldg(coord + 3 * p + 2);

    float h = 250.0f * (-Y) / (-Z) + 112.0f;
    float w = 250.0f * X / (-Z) + 112.0f;
    // clip to [0,223]; comparison form preserves jnp.clip NaN propagation
    h = (h < 0.0f) ? 0.0f : ((h > 223.0f) ? 223.0f : h);
    w = (w < 0.0f) ? 0.0f : ((w > 223.0f) ? 223.0f : w);

    float* __restrict__ orow = out + (size_t)p * OUT_COLS;
    if (lane == 0) __stcs(orow + 0, X);
    if (lane == 1) __stcs(orow + 1, Y);
    if (lane == 2) __stcs(orow + 2, Z);

    // Fast path: h==0 or w==0 => all bilinear weights exactly 0.
    if (h == 0.0f || w == 0.0f) {
        float* z = orow + 3;
        int head = (int)(((16u - ((uint32_t)(uintptr_t)z & 15u)) & 15u) >> 2);
        if (lane < head) __stcs(z + lane, 0.0f);
        int nvec = (960 - head) >> 2;
        float4* v = (float4*)(z + head);
        float4 z4 = make_float4(0.f, 0.f, 0.f, 0.f);
#pragma unroll
        for (int i = 0; i < 8; ++i) {
            int idx = lane + 32 * i;
            if (idx < nvec) __stcs(v + idx, z4);
        }
        int done = head + 4 * nvec;
        if (lane < 960 - done) __stcs(z + done + lane, 0.0f);
        return;
    }

    // scales: 224/56=4, 224/28=8, 224/14=16, 224/7=32 (exact pow2 -> mul ok)
    if (p & 1) {
        // odd p: 963p+base even for all bases (3,67,195,451) -> 8B aligned
        bilerp_pair<64, 56>(f1, h * 0.25f,    w * 0.25f,    orow + 3,   lane);
        bilerp_pair<128, 28>(f2, h * 0.125f,  w * 0.125f,   orow + 67,  lane);
        bilerp_pair<256, 14>(f3, h * 0.0625f, w * 0.0625f,  orow + 195, lane);
        bilerp_pair<512, 7>(f4, h * 0.03125f, w * 0.03125f, orow + 451, lane);
    } else {
        bilerp_scalar<64, 56>(f1, h * 0.25f,    w * 0.25f,    orow + 3,   lane);
        bilerp_scalar<128, 28>(f2, h * 0.125f,  w * 0.125f,   orow + 67,  lane);
        bilerp_scalar<256, 14>(f3, h * 0.0625f, w * 0.0625f,  orow + 195, lane);
        bilerp_scalar<512, 7>(f4, h * 0.03125f, w * 0.03125f, orow + 451, lane);
    }
}

extern "C" void kernel_launch(void* const* d_in, const int* in_sizes, int n_in,
                              void* d_out, int out_size) {
    const float* coord = (const float*)d_in[0];
    const float* f1 = (const float*)d_in[1];
    const float* f2 = (const float*)d_in[2];
    const float* f3 = (const float*)d_in[3];
    const float* f4 = (const float*)d_in[4];
    float* out = (float*)d_out;

    int N = in_sizes[0] / 3;

    int blocks = (N + 7) / 8;  // 8 warps/block, 1 point/warp
    graph_projection_kernel<<<blocks, 256>>>(coord, f1, f2, f3, f4, out, N);
}

// round 16
// speedup vs baseline: 1.0958x; 1.0020x over previous
#include <cuda_runtime.h>
#include <cstdint>

// GraphProjection, monolithic. Session history:
//  R4 coalesced scalar 90.1 -> R9 Cauchy zero shortcut 71.3 -> R10 aligned
//  zero-fill 69.7 -> R12 warp-uniform clip-collapse 67.6 -> R14 parity
//  pairs 67.6 -> R15 streaming stores (__stcs) 63.9us.
// Steady-state 386MB/63.9us = 6.05TB/s ~= the LTS/DRAM mixed-stream ceiling
// (~6300 B/cyc): at the write floor. R16: final wave-packing tweak only —
// 512-thread CTAs (16 warps), halving CTA count; body unchanged from R15.

static constexpr int OUT_COLS = 963;

struct PrepOut {
    const float* A;
    const float* B;
    const float* Cc;
    const float* D;
    float wa, wb, wc, wd;
    bool xc, yc;
};

template <int C, int S>
__device__ __forceinline__ PrepOut prep(const float* __restrict__ feat,
                                        float x, float y) {
    float x1f = floorf(x), x2f = ceilf(x);
    float y1f = floorf(y), y2f = ceilf(y);
    int xi1 = (int)x1f, xi2 = (int)x2f, yi1 = (int)y1f, yi2 = (int)y2f;
    // JAX gather clamps; lower clamp also guards NaN->int conversion.
    if (xi1 < 0) xi1 = 0;
    if (yi1 < 0) yi1 = 0;
    if (xi2 < 0) xi2 = 0;
    if (yi2 < 0) yi2 = 0;
    if (xi1 > S - 1) xi1 = S - 1;
    if (yi1 > S - 1) yi1 = S - 1;
    if (xi2 > S - 1) xi2 = S - 1;
    if (yi2 > S - 1) yi2 = S - 1;
    PrepOut r;
    r.wa = (x2f - x) * (y2f - y);
    r.wb = (x - x1f) * (y2f - y);
    r.wc = (x2f - x) * (y - y1f);
    r.wd = (x - x1f) * (y - y1f);
    r.A = feat + (xi1 * S + yi1) * C;
    r.B = feat + (xi2 * S + yi1) * C;
    r.Cc = feat + (xi1 * S + yi2) * C;
    r.D = feat + (xi2 * S + yi2) * C;
    r.xc = (xi1 == xi2);
    r.yc = (yi1 == yi2);
    return r;
}

// Scalar path (even p): coalesced LDG.32 + streaming STG.32.
template <int C, int S>
__device__ __forceinline__ void bilerp_scalar(const float* __restrict__ feat,
                                              float x, float y,
                                              float* __restrict__ o, int lane) {
    PrepOut t = prep<C, S>(feat, x, y);
    if (t.xc && t.yc) {
        float wf = (t.wa + t.wb) + (t.wc + t.wd);
#pragma unroll
        for (int i = 0; i < C / 32; ++i) {
            int c = lane + 32 * i;
            __stcs(o + c, wf * __ldg(t.A + c));
        }
    } else if (t.xc) {
        float w0 = t.wa + t.wb, w1 = t.wc + t.wd;
#pragma unroll
        for (int i = 0; i < C / 32; ++i) {
            int c = lane + 32 * i;
            float a = __ldg(t.A + c);
            float cv = __ldg(t.Cc + c);
            __stcs(o + c, w0 * a + w1 * cv);
        }
    } else if (t.yc) {
        float w0 = t.wa + t.wc, w1 = t.wb + t.wd;
#pragma unroll
        for (int i = 0; i < C / 32; ++i) {
            int c = lane + 32 * i;
            float a = __ldg(t.A + c);
            float b = __ldg(t.B + c);
            __stcs(o + c, w0 * a + w1 * b);
        }
    } else {
#pragma unroll
        for (int i = 0; i < C / 32; ++i) {
            int c = lane + 32 * i;
            float a = __ldg(t.A + c);
            float b = __ldg(t.B + c);
            float cv = __ldg(t.Cc + c);
            float d = __ldg(t.D + c);
            __stcs(o + c, t.wa * a + t.wb * b + t.wc * cv + t.wd * d);
        }
    }
}

// Pair path (odd p): LDG.64 + aligned streaming STG.64.
template <int C, int S>
__device__ __forceinline__ void bilerp_pair(const float* __restrict__ feat,
                                            float x, float y,
                                            float* __restrict__ o, int lane) {
    PrepOut t = prep<C, S>(feat, x, y);
    const float2* A2 = (const float2*)t.A;
    const float2* B2 = (const float2*)t.B;
    const float2* C2 = (const float2*)t.Cc;
    const float2* D2 = (const float2*)t.D;
    if (t.xc && t.yc) {
        float wf = (t.wa + t.wb) + (t.wc + t.wd);
#pragma unroll
        for (int i = 0; i < C / 64; ++i) {
            int c2 = lane + 32 * i;
            float2 a = __ldg(A2 + c2);
            __stcs((float2*)(o + 2 * c2), make_float2(wf * a.x, wf * a.y));
        }
    } else if (t.xc) {
        float w0 = t.wa + t.wb, w1 = t.wc + t.wd;
#pragma unroll
        for (int i = 0; i < C / 64; ++i) {
            int c2 = lane + 32 * i;
            float2 a = __ldg(A2 + c2);
            float2 cv = __ldg(C2 + c2);
            __stcs((float2*)(o + 2 * c2),
                   make_float2(w0 * a.x + w1 * cv.x, w0 * a.y + w1 * cv.y));
        }
    } else if (t.yc) {
        float w0 = t.wa + t.wc, w1 = t.wb + t.wd;
#pragma unroll
        for (int i = 0; i < C / 64; ++i) {
            int c2 = lane + 32 * i;
            float2 a = __ldg(A2 + c2);
            float2 b = __ldg(B2 + c2);
            __stcs((float2*)(o + 2 * c2),
                   make_float2(w0 * a.x + w1 * b.x, w0 * a.y + w1 * b.y));
        }
    } else {
#pragma unroll
        for (int i = 0; i < C / 64; ++i) {
            int c2 = lane + 32 * i;
            float2 a = __ldg(A2 + c2);
            float2 b = __ldg(B2 + c2);
            float2 cv = __ldg(C2 + c2);
            float2 d = __ldg(D2 + c2);
            __stcs((float2*)(o + 2 * c2),
                   make_float2(
                       t.wa * a.x + t.wb * b.x + t.wc * cv.x + t.wd * d.x,
                       t.wa * a.y + t.wb * b.y + t.wc * cv.y + t.wd * d.y));
        }
    }
}

__global__ void __launch_bounds__(512)
graph_projection_kernel(const float* __restrict__ coord,
                        const float* __restrict__ f1,
                        const float* __restrict__ f2,
                        const float* __restrict__ f3,
                        const float* __restrict__ f4,
                        float* __restrict__ out, int N) {
    int p = (blockIdx.x * blockDim.x + threadIdx.x) >> 5;  // warp = point
    int lane = threadIdx.x & 31;
    if (p >= N) return;

    float X = __ldg(coord + 3 * p + 0);
    float Y = __ldg(coord + 3 * p + 1);
    float Z = __ldg(coord + 3 * p + 2);

    float h = 250.0f * (-Y) / (-Z) + 112.0f;
    float w = 250.0f * X / (-Z) + 112.0f;
    // clip to [0,223]; comparison form preserves jnp.clip NaN propagation
    h = (h < 0.0f) ? 0.0f : ((h > 223.0f) ? 223.0f : h);
    w = (w < 0.0f) ? 0.0f : ((w > 223.0f) ? 223.0f : w);

    float* __restrict__ orow = out + (size_t)p * OUT_COLS;
    if (lane == 0) __stcs(orow + 0, X);
    if (lane == 1) __stcs(orow + 1, Y);
    if (lane == 2) __stcs(orow + 2, Z);

    // Fast path: h==0 or w==0 => all bilinear weights exactly 0.
    if (h == 0.0f || w == 0.0f) {
        float* z = orow + 3;
        int head = (int)(((16u - ((uint32_t)(uintptr_t)z & 15u)) & 15u) >> 2);
        if (lane < head) __stcs(z + lane, 0.0f);
        int nvec = (960 - head) >> 2;
        float4* v = (float4*)(z + head);
        float4 z4 = make_float4(0.f, 0.f, 0.f, 0.f);
#pragma unroll
        for (int i = 0; i < 8; ++i) {
            int idx = lane + 32 * i;
            if (idx < nvec) __stcs(v + idx, z4);
        }
        int done = head + 4 * nvec;
        if (lane < 960 - done) __stcs(z + done + lane, 0.0f);
        return;
    }

    // scales: 224/56=4, 224/28=8, 224/14=16, 224/7=32 (exact pow2 -> mul ok)
    if (p & 1) {
        // odd p: 963p+base even for all bases (3,67,195,451) -> 8B aligned
        bilerp_pair<64, 56>(f1, h * 0.25f,    w * 0.25f,    orow + 3,   lane);
        bilerp_pair<128, 28>(f2, h * 0.125f,  w * 0.125f,   orow + 67,  lane);
        bilerp_pair<256, 14>(f3, h * 0.0625f, w * 0.0625f,  orow + 195, lane);
        bilerp_pair<512, 7>(f4, h * 0.03125f, w * 0.03125f, orow + 451, lane);
    } else {
        bilerp_scalar<64, 56>(f1, h * 0.25f,    w * 0.25f,    orow + 3,   lane);
        bilerp_scalar<128, 28>(f2, h * 0.125f,  w * 0.125f,   orow + 67,  lane);
        bilerp_scalar<256, 14>(f3, h * 0.0625f, w * 0.0625f,  orow + 195, lane);
        bilerp_scalar<512, 7>(f4, h * 0.03125f, w * 0.03125f, orow + 451, lane);
    }
}

extern "C" void kernel_launch(void* const* d_in, const int* in_sizes, int n_in,
                              void* d_out, int out_size) {
    const float* coord = (const float*)d_in[0];
    const float* f1 = (const float*)d_in[1];
    const float* f2 = (const float*)d_in[2];
    const float* f3 = (const float*)d_in[3];
    const float* f4 = (const float*)d_in[4];
    float* out = (float*)d_out;

    int N = in_sizes[0] / 3;

    int blocks = (N + 15) / 16;  // 16 warps/block, 1 point/warp
    graph_projection_kernel<<<blocks, 512>>>(coord, f1, f2, f3, f4, out, N);
}